// round 1
// baseline (speedup 1.0000x reference)
#include <cuda_runtime.h>

#define NN 100000
#define NE 640000
#define INC 256
#define HID 128
#define OUTC 64

// Scratch (allocation-free rule: __device__ globals)
__device__ float g_h[(size_t)NN * HID];   // pre-propagation features (h1, later h2pre)
__device__ float g_p[(size_t)NN * HID];   // propagated hidden
__device__ float g_dinv[NN];              // degree, then d^{-1/2}

// ---------------------------------------------------------------------------
// Degree / normalization
// ---------------------------------------------------------------------------
__global__ void k_deg_init() {
    int n = blockIdx.x * blockDim.x + threadIdx.x;
    if (n < NN) g_dinv[n] = 1.0f;  // self-loop
}

__global__ void k_deg_count(const int* __restrict__ dst) {
    int e = blockIdx.x * blockDim.x + threadIdx.x;
    if (e < NE) atomicAdd(&g_dinv[dst[e]], 1.0f);
}

__global__ void k_rsqrt() {
    int n = blockIdx.x * blockDim.x + threadIdx.x;
    if (n < NN) g_dinv[n] = rsqrtf(g_dinv[n]);
}

// ---------------------------------------------------------------------------
// FP32 SGEMM: C[M,128] = op(A[M,KT]) @ B[KT,128]
// B is given as two halves (cols 0..63 from B0, 64..127 from B1), each with
// row stride ldb. For a single 128-wide B pass (B0=W, B1=W+64, ldb=128).
// RELU applies relu to A elements on load.
// Block: 256 threads, tile 128(M) x 128(N), per-thread 8x8.
// ---------------------------------------------------------------------------
template <int KT, bool RELU>
__global__ __launch_bounds__(256) void sgemm128(
    const float* __restrict__ A,
    const float* __restrict__ B0, const float* __restrict__ B1, int ldb,
    float* __restrict__ C, int M)
{
    __shared__ float As[16][128];  // [k][m]
    __shared__ float Bs[16][128];  // [k][n]

    const int t = threadIdx.x;
    const int tx = t & 15;         // n-dim thread coord
    const int ty = t >> 4;         // m-dim thread coord
    const int blockRow = blockIdx.x * 128;

    // A tile load mapping: thread loads row (t>>1), k-offset (t&1)*8 (2 float4)
    const int ar = t >> 1;
    const int ak = (t & 1) * 8;
    const int grow = blockRow + ar;
    const bool arow_ok = (grow < M);
    const float* aptr = A + (size_t)grow * KT + ak;

    // B tile load mapping: thread loads k-row (t>>4), cols (t&15)*8 (2 float4)
    const int bk = t >> 4;
    const int bn = (t & 15) * 8;
    const float* bptr = (bn < 64) ? (B0 + bn) : (B1 + (bn - 64));

    float acc[8][8];
#pragma unroll
    for (int i = 0; i < 8; i++)
#pragma unroll
        for (int j = 0; j < 8; j++) acc[i][j] = 0.0f;

#pragma unroll 1
    for (int kt = 0; kt < KT; kt += 16) {
        float4 a0 = make_float4(0.f, 0.f, 0.f, 0.f), a1 = a0;
        if (arow_ok) {
            a0 = *(const float4*)(aptr + kt);
            a1 = *(const float4*)(aptr + kt + 4);
        }
        if (RELU) {
            a0.x = fmaxf(a0.x, 0.f); a0.y = fmaxf(a0.y, 0.f);
            a0.z = fmaxf(a0.z, 0.f); a0.w = fmaxf(a0.w, 0.f);
            a1.x = fmaxf(a1.x, 0.f); a1.y = fmaxf(a1.y, 0.f);
            a1.z = fmaxf(a1.z, 0.f); a1.w = fmaxf(a1.w, 0.f);
        }
        const float4 b0 = *(const float4*)(bptr + (size_t)(kt + bk) * ldb);
        const float4 b1 = *(const float4*)(bptr + (size_t)(kt + bk) * ldb + 4);

        __syncthreads();  // previous iteration's compute done
        // store A transposed: As[k][m]
        As[ak + 0][ar] = a0.x; As[ak + 1][ar] = a0.y;
        As[ak + 2][ar] = a0.z; As[ak + 3][ar] = a0.w;
        As[ak + 4][ar] = a1.x; As[ak + 5][ar] = a1.y;
        As[ak + 6][ar] = a1.z; As[ak + 7][ar] = a1.w;
        *(float4*)&Bs[bk][bn] = b0;
        *(float4*)&Bs[bk][bn + 4] = b1;
        __syncthreads();

#pragma unroll
        for (int kk = 0; kk < 16; kk++) {
            float4 fa0 = *(const float4*)&As[kk][ty * 8];
            float4 fa1 = *(const float4*)&As[kk][ty * 8 + 4];
            float4 fb0 = *(const float4*)&Bs[kk][tx * 8];
            float4 fb1 = *(const float4*)&Bs[kk][tx * 8 + 4];
            float a[8] = {fa0.x, fa0.y, fa0.z, fa0.w, fa1.x, fa1.y, fa1.z, fa1.w};
            float b[8] = {fb0.x, fb0.y, fb0.z, fb0.w, fb1.x, fb1.y, fb1.z, fb1.w};
#pragma unroll
            for (int i = 0; i < 8; i++)
#pragma unroll
                for (int j = 0; j < 8; j++)
                    acc[i][j] = fmaf(a[i], b[j], acc[i][j]);
        }
    }

#pragma unroll
    for (int i = 0; i < 8; i++) {
        int row = blockRow + ty * 8 + i;
        if (row < M) {
            float4 c0 = make_float4(acc[i][0], acc[i][1], acc[i][2], acc[i][3]);
            float4 c1 = make_float4(acc[i][4], acc[i][5], acc[i][6], acc[i][7]);
            *(float4*)(C + (size_t)row * 128 + tx * 8) = c0;
            *(float4*)(C + (size_t)row * 128 + tx * 8 + 4) = c1;
        }
    }
}

// ---------------------------------------------------------------------------
// Propagation: init with bias + self-loop term, then edge atomics
// ---------------------------------------------------------------------------
__global__ void k_prop_init(const float* __restrict__ H,
                            const float* __restrict__ b,
                            float* __restrict__ out)
{
    int idx = blockIdx.x * blockDim.x + threadIdx.x;
    if (idx >= NN * 32) return;
    int n = idx >> 5, g = idx & 31;
    float di = g_dinv[n];
    float s = di * di;
    float4 v = ((const float4*)(H + (size_t)n * HID))[g];
    float4 bb = ((const float4*)b)[g];
    float4 o = make_float4(fmaf(v.x, s, bb.x), fmaf(v.y, s, bb.y),
                           fmaf(v.z, s, bb.z), fmaf(v.w, s, bb.w));
    ((float4*)(out + (size_t)n * HID))[g] = o;
}

__global__ void k_prop_edges(const float* __restrict__ H,
                             float* __restrict__ out,
                             const int* __restrict__ src,
                             const int* __restrict__ dst)
{
    int idx = blockIdx.x * blockDim.x + threadIdx.x;
    if (idx >= NE * 32) return;
    int e = idx >> 5, g = idx & 31;
    int s = src[e], d = dst[e];
    float nm = g_dinv[s] * g_dinv[d];
    float4 v = ((const float4*)(H + (size_t)s * HID))[g];
    float* o = out + (size_t)d * HID + g * 4;
    atomicAdd(o + 0, v.x * nm);
    atomicAdd(o + 1, v.y * nm);
    atomicAdd(o + 2, v.z * nm);
    atomicAdd(o + 3, v.w * nm);
}

// Layer-2 output: cols 0..63 -> mu at out[n*64+c], 64..127 -> logvar at out[NN*64 + n*64 + c-64]
__global__ void k_out_init(const float* __restrict__ H,
                           const float* __restrict__ bmu,
                           const float* __restrict__ blv,
                           float* __restrict__ out)
{
    int idx = blockIdx.x * blockDim.x + threadIdx.x;
    if (idx >= NN * 32) return;
    int n = idx >> 5, g = idx & 31;
    float di = g_dinv[n];
    float s = di * di;
    float4 v = ((const float4*)(H + (size_t)n * HID))[g];
    float4 bb;
    float* dstp;
    if (g < 16) {
        bb = ((const float4*)bmu)[g];
        dstp = out + (size_t)n * 64 + g * 4;
    } else {
        bb = ((const float4*)blv)[g - 16];
        dstp = out + (size_t)NN * 64 + (size_t)n * 64 + (g - 16) * 4;
    }
    float4 o = make_float4(fmaf(v.x, s, bb.x), fmaf(v.y, s, bb.y),
                           fmaf(v.z, s, bb.z), fmaf(v.w, s, bb.w));
    *(float4*)dstp = o;
}

__global__ void k_prop_edges_out(const float* __restrict__ H,
                                 float* __restrict__ out,
                                 const int* __restrict__ src,
                                 const int* __restrict__ dst)
{
    int idx = blockIdx.x * blockDim.x + threadIdx.x;
    if (idx >= NE * 32) return;
    int e = idx >> 5, g = idx & 31;
    int s = src[e], d = dst[e];
    float nm = g_dinv[s] * g_dinv[d];
    float4 v = ((const float4*)(H + (size_t)s * HID))[g];
    float* o = (g < 16)
        ? out + (size_t)d * 64 + g * 4
        : out + (size_t)NN * 64 + (size_t)d * 64 + (g - 16) * 4;
    atomicAdd(o + 0, v.x * nm);
    atomicAdd(o + 1, v.y * nm);
    atomicAdd(o + 2, v.z * nm);
    atomicAdd(o + 3, v.w * nm);
}

// ---------------------------------------------------------------------------
extern "C" void kernel_launch(void* const* d_in, const int* in_sizes, int n_in,
                              void* d_out, int out_size)
{
    const float* x   = (const float*)d_in[0];
    const int*   ei  = (const int*)d_in[1];
    const float* W1  = (const float*)d_in[2];
    const float* b1  = (const float*)d_in[3];
    const float* Wmu = (const float*)d_in[4];
    const float* bmu = (const float*)d_in[5];
    const float* Wlv = (const float*)d_in[6];
    const float* blv = (const float*)d_in[7];
    float* out = (float*)d_out;

    const int* src = ei;
    const int* dst = ei + NE;

    float *h_ptr, *p_ptr;
    cudaGetSymbolAddress((void**)&h_ptr, g_h);
    cudaGetSymbolAddress((void**)&p_ptr, g_p);

    const int TB = 256;
    // Degree / normalization
    k_deg_init<<<(NN + TB - 1) / TB, TB>>>();
    k_deg_count<<<(NE + TB - 1) / TB, TB>>>(dst);
    k_rsqrt<<<(NN + TB - 1) / TB, TB>>>();

    // Layer 1: h1 = x @ W1  (K=256, N=128)
    sgemm128<INC, false><<<(NN + 127) / 128, 256>>>(x, W1, W1 + 64, 128, h_ptr, NN);

    // Propagate: g_p = b1 + D^-1/2 A_hat D^-1/2 h1
    k_prop_init<<<(NN * 32 + TB - 1) / TB, TB>>>(h_ptr, b1, p_ptr);
    k_prop_edges<<<(NE * 32 + TB - 1) / TB, TB>>>(h_ptr, p_ptr, src, dst);

    // Layer 2 pre: h2 = relu(g_p) @ [W_mu | W_logvar]  (K=128, N=128)
    sgemm128<HID, true><<<(NN + 127) / 128, 256>>>(p_ptr, Wmu, Wlv, 64, h_ptr, NN);

    // Propagate concatenated output directly into d_out (mu | logvar split)
    k_out_init<<<(NN * 32 + TB - 1) / TB, TB>>>(h_ptr, bmu, blv, out);
    k_prop_edges_out<<<(NE * 32 + TB - 1) / TB, TB>>>(h_ptr, out, src, dst);
}

// round 2
// speedup vs baseline: 1.2343x; 1.2343x over previous
#include <cuda_runtime.h>

#define NN 100000
#define NE 640000
#define INC 256
#define HID 128

// Scratch (__device__ globals — allocation-free rule)
__device__ float g_h[(size_t)NN * HID];   // pre-propagation features
__device__ float g_p[(size_t)NN * HID];   // propagated hidden
__device__ float g_dinv[NN];              // d^{-1/2}
__device__ int   g_cnt[NN];               // in-degree (excl self)
__device__ int   g_off[NN + 1];           // CSR offsets
__device__ int   g_cursor[NN];            // scatter cursors
__device__ int   g_es[NE];                // CSR src ids (sorted by dst)
__device__ float g_en[NE];                // CSR edge norms

// ---------------------------------------------------------------------------
// CSR construction
// ---------------------------------------------------------------------------
__global__ void k_cnt_zero() {
    int n = blockIdx.x * blockDim.x + threadIdx.x;
    if (n < NN) g_cnt[n] = 0;
}

__global__ void k_count(const int* __restrict__ dst) {
    int e = blockIdx.x * blockDim.x + threadIdx.x;
    if (e < NE) atomicAdd(&g_cnt[dst[e]], 1);
}

__global__ void k_dinv() {
    int n = blockIdx.x * blockDim.x + threadIdx.x;
    if (n < NN) g_dinv[n] = rsqrtf(1.0f + (float)g_cnt[n]);  // +1 self-loop
}

// Single-block prefix scan over NN counts -> offsets (+cursor copy)
__global__ __launch_bounds__(1024) void k_scan() {
    __shared__ int sm[1024];
    const int t = threadIdx.x;
    const int CH = (NN + 1023) / 1024;  // 98
    const int base = t * CH;
    int local = 0;
    for (int i = 0; i < CH; i++) {
        int idx = base + i;
        if (idx < NN) local += g_cnt[idx];
    }
    sm[t] = local;
    __syncthreads();
    // Hillis-Steele inclusive scan
    for (int d = 1; d < 1024; d <<= 1) {
        int v = (t >= d) ? sm[t - d] : 0;
        __syncthreads();
        sm[t] += v;
        __syncthreads();
    }
    int run = (t == 0) ? 0 : sm[t - 1];
    for (int i = 0; i < CH; i++) {
        int idx = base + i;
        if (idx < NN) {
            g_off[idx] = run;
            g_cursor[idx] = run;
            run += g_cnt[idx];
        }
    }
    if (t == 1023) g_off[NN] = NE;
}

__global__ void k_scatter(const int* __restrict__ src, const int* __restrict__ dst) {
    int e = blockIdx.x * blockDim.x + threadIdx.x;
    if (e >= NE) return;
    int s = src[e], d = dst[e];
    int pos = atomicAdd(&g_cursor[d], 1);
    g_es[pos] = s;
    g_en[pos] = g_dinv[s] * g_dinv[d];
}

// ---------------------------------------------------------------------------
// FP32 SGEMM: C[M,128] = op(A[M,KT]) @ B[KT,128]   (unchanged from R1)
// ---------------------------------------------------------------------------
template <int KT, bool RELU>
__global__ __launch_bounds__(256) void sgemm128(
    const float* __restrict__ A,
    const float* __restrict__ B0, const float* __restrict__ B1, int ldb,
    float* __restrict__ C, int M)
{
    __shared__ float As[16][128];
    __shared__ float Bs[16][128];

    const int t = threadIdx.x;
    const int tx = t & 15;
    const int ty = t >> 4;
    const int blockRow = blockIdx.x * 128;

    const int ar = t >> 1;
    const int ak = (t & 1) * 8;
    const int grow = blockRow + ar;
    const bool arow_ok = (grow < M);
    const float* aptr = A + (size_t)grow * KT + ak;

    const int bk = t >> 4;
    const int bn = (t & 15) * 8;
    const float* bptr = (bn < 64) ? (B0 + bn) : (B1 + (bn - 64));

    float acc[8][8];
#pragma unroll
    for (int i = 0; i < 8; i++)
#pragma unroll
        for (int j = 0; j < 8; j++) acc[i][j] = 0.0f;

#pragma unroll 1
    for (int kt = 0; kt < KT; kt += 16) {
        float4 a0 = make_float4(0.f, 0.f, 0.f, 0.f), a1 = a0;
        if (arow_ok) {
            a0 = *(const float4*)(aptr + kt);
            a1 = *(const float4*)(aptr + kt + 4);
        }
        if (RELU) {
            a0.x = fmaxf(a0.x, 0.f); a0.y = fmaxf(a0.y, 0.f);
            a0.z = fmaxf(a0.z, 0.f); a0.w = fmaxf(a0.w, 0.f);
            a1.x = fmaxf(a1.x, 0.f); a1.y = fmaxf(a1.y, 0.f);
            a1.z = fmaxf(a1.z, 0.f); a1.w = fmaxf(a1.w, 0.f);
        }
        const float4 b0 = *(const float4*)(bptr + (size_t)(kt + bk) * ldb);
        const float4 b1 = *(const float4*)(bptr + (size_t)(kt + bk) * ldb + 4);

        __syncthreads();
        As[ak + 0][ar] = a0.x; As[ak + 1][ar] = a0.y;
        As[ak + 2][ar] = a0.z; As[ak + 3][ar] = a0.w;
        As[ak + 4][ar] = a1.x; As[ak + 5][ar] = a1.y;
        As[ak + 6][ar] = a1.z; As[ak + 7][ar] = a1.w;
        *(float4*)&Bs[bk][bn] = b0;
        *(float4*)&Bs[bk][bn + 4] = b1;
        __syncthreads();

#pragma unroll
        for (int kk = 0; kk < 16; kk++) {
            float4 fa0 = *(const float4*)&As[kk][ty * 8];
            float4 fa1 = *(const float4*)&As[kk][ty * 8 + 4];
            float4 fb0 = *(const float4*)&Bs[kk][tx * 8];
            float4 fb1 = *(const float4*)&Bs[kk][tx * 8 + 4];
            float a[8] = {fa0.x, fa0.y, fa0.z, fa0.w, fa1.x, fa1.y, fa1.z, fa1.w};
            float b[8] = {fb0.x, fb0.y, fb0.z, fb0.w, fb1.x, fb1.y, fb1.z, fb1.w};
#pragma unroll
            for (int i = 0; i < 8; i++)
#pragma unroll
                for (int j = 0; j < 8; j++)
                    acc[i][j] = fmaf(a[i], b[j], acc[i][j]);
        }
    }

#pragma unroll
    for (int i = 0; i < 8; i++) {
        int row = blockRow + ty * 8 + i;
        if (row < M) {
            float4 c0 = make_float4(acc[i][0], acc[i][1], acc[i][2], acc[i][3]);
            float4 c1 = make_float4(acc[i][4], acc[i][5], acc[i][6], acc[i][7]);
            *(float4*)(C + (size_t)row * 128 + tx * 8) = c0;
            *(float4*)(C + (size_t)row * 128 + tx * 8 + 4) = c1;
        }
    }
}

// ---------------------------------------------------------------------------
// CSR propagation: warp per node, lane owns 4 channels. No atomics.
// out[n] = b + dinv[n]^2 * H[n] + sum_e norm[e] * H[src[e]]
// ---------------------------------------------------------------------------
__global__ __launch_bounds__(256) void k_prop_csr(
    const float* __restrict__ H,
    const float* __restrict__ b,
    float* __restrict__ out)
{
    int warp = (blockIdx.x * blockDim.x + threadIdx.x) >> 5;
    if (warp >= NN) return;
    int lane = threadIdx.x & 31;

    float di = g_dinv[warp];
    float s = di * di;
    float4 bb = ((const float4*)b)[lane];
    float4 v = ((const float4*)(H + (size_t)warp * HID))[lane];
    float ax = fmaf(v.x, s, bb.x);
    float ay = fmaf(v.y, s, bb.y);
    float az = fmaf(v.z, s, bb.z);
    float aw = fmaf(v.w, s, bb.w);

    int e = g_off[warp];
    const int end = g_off[warp + 1];
    for (; e + 1 < end; e += 2) {
        int s0 = g_es[e],     s1 = g_es[e + 1];
        float n0 = g_en[e],   n1 = g_en[e + 1];
        float4 v0 = ((const float4*)(H + (size_t)s0 * HID))[lane];
        float4 v1 = ((const float4*)(H + (size_t)s1 * HID))[lane];
        ax = fmaf(v0.x, n0, ax); ay = fmaf(v0.y, n0, ay);
        az = fmaf(v0.z, n0, az); aw = fmaf(v0.w, n0, aw);
        ax = fmaf(v1.x, n1, ax); ay = fmaf(v1.y, n1, ay);
        az = fmaf(v1.z, n1, az); aw = fmaf(v1.w, n1, aw);
    }
    if (e < end) {
        int s0 = g_es[e];
        float n0 = g_en[e];
        float4 v0 = ((const float4*)(H + (size_t)s0 * HID))[lane];
        ax = fmaf(v0.x, n0, ax); ay = fmaf(v0.y, n0, ay);
        az = fmaf(v0.z, n0, az); aw = fmaf(v0.w, n0, aw);
    }

    ((float4*)(out + (size_t)warp * HID))[lane] = make_float4(ax, ay, az, aw);
}

// Layer-2 variant: lanes 0..15 -> mu, 16..31 -> logvar (split output)
__global__ __launch_bounds__(256) void k_prop_csr_out(
    const float* __restrict__ H,
    const float* __restrict__ bmu,
    const float* __restrict__ blv,
    float* __restrict__ out)
{
    int warp = (blockIdx.x * blockDim.x + threadIdx.x) >> 5;
    if (warp >= NN) return;
    int lane = threadIdx.x & 31;

    float di = g_dinv[warp];
    float s = di * di;
    float4 bb;
    float* dstp;
    if (lane < 16) {
        bb = ((const float4*)bmu)[lane];
        dstp = out + (size_t)warp * 64 + lane * 4;
    } else {
        bb = ((const float4*)blv)[lane - 16];
        dstp = out + (size_t)NN * 64 + (size_t)warp * 64 + (lane - 16) * 4;
    }
    float4 v = ((const float4*)(H + (size_t)warp * HID))[lane];
    float ax = fmaf(v.x, s, bb.x);
    float ay = fmaf(v.y, s, bb.y);
    float az = fmaf(v.z, s, bb.z);
    float aw = fmaf(v.w, s, bb.w);

    int e = g_off[warp];
    const int end = g_off[warp + 1];
    for (; e + 1 < end; e += 2) {
        int s0 = g_es[e],     s1 = g_es[e + 1];
        float n0 = g_en[e],   n1 = g_en[e + 1];
        float4 v0 = ((const float4*)(H + (size_t)s0 * HID))[lane];
        float4 v1 = ((const float4*)(H + (size_t)s1 * HID))[lane];
        ax = fmaf(v0.x, n0, ax); ay = fmaf(v0.y, n0, ay);
        az = fmaf(v0.z, n0, az); aw = fmaf(v0.w, n0, aw);
        ax = fmaf(v1.x, n1, ax); ay = fmaf(v1.y, n1, ay);
        az = fmaf(v1.z, n1, az); aw = fmaf(v1.w, n1, aw);
    }
    if (e < end) {
        int s0 = g_es[e];
        float n0 = g_en[e];
        float4 v0 = ((const float4*)(H + (size_t)s0 * HID))[lane];
        ax = fmaf(v0.x, n0, ax); ay = fmaf(v0.y, n0, ay);
        az = fmaf(v0.z, n0, az); aw = fmaf(v0.w, n0, aw);
    }

    *(float4*)dstp = make_float4(ax, ay, az, aw);
}

// ---------------------------------------------------------------------------
extern "C" void kernel_launch(void* const* d_in, const int* in_sizes, int n_in,
                              void* d_out, int out_size)
{
    const float* x   = (const float*)d_in[0];
    const int*   ei  = (const int*)d_in[1];
    const float* W1  = (const float*)d_in[2];
    const float* b1  = (const float*)d_in[3];
    const float* Wmu = (const float*)d_in[4];
    const float* bmu = (const float*)d_in[5];
    const float* Wlv = (const float*)d_in[6];
    const float* blv = (const float*)d_in[7];
    float* out = (float*)d_out;

    const int* src = ei;
    const int* dst = ei + NE;

    float *h_ptr, *p_ptr;
    cudaGetSymbolAddress((void**)&h_ptr, g_h);
    cudaGetSymbolAddress((void**)&p_ptr, g_p);

    const int TB = 256;

    // --- CSR build ---
    k_cnt_zero<<<(NN + TB - 1) / TB, TB>>>();
    k_count<<<(NE + TB - 1) / TB, TB>>>(dst);
    k_dinv<<<(NN + TB - 1) / TB, TB>>>();
    k_scan<<<1, 1024>>>();
    k_scatter<<<(NE + TB - 1) / TB, TB>>>(src, dst);

    // --- Layer 1: h1 = x @ W1 ---
    sgemm128<INC, false><<<(NN + 127) / 128, 256>>>(x, W1, W1 + 64, 128, h_ptr, NN);

    // --- Propagate hidden (CSR, no atomics) ---
    k_prop_csr<<<(NN * 32 + TB - 1) / TB, TB>>>(h_ptr, b1, p_ptr);

    // --- Layer 2 pre: h2 = relu(p) @ [W_mu | W_logvar] ---
    sgemm128<HID, true><<<(NN + 127) / 128, 256>>>(p_ptr, Wmu, Wlv, 64, h_ptr, NN);

    // --- Propagate to split output ---
    k_prop_csr_out<<<(NN * 32 + TB - 1) / TB, TB>>>(h_ptr, bmu, blv, out);
}

// round 3
// speedup vs baseline: 1.6899x; 1.3690x over previous
#include <cuda_runtime.h>

#define NN 100000
#define NE 640000
#define INC 256
#define HID 128
#define NB  ((NN + 1023) / 1024)   // 98 scan blocks

// Scratch (__device__ globals — allocation-free rule)
__device__ float g_h[(size_t)NN * HID];
__device__ float g_p[(size_t)NN * HID];
__device__ float g_dinv[NN];
__device__ int   g_cnt[NN];
__device__ int   g_off[NN + 1];
__device__ int   g_cursor[NN];
__device__ int   g_es[NE];
__device__ float g_en[NE];
__device__ int   g_bsum[128];   // block partial sums (NB=98 <= 128)

// ---------------------------------------------------------------------------
// CSR construction
// ---------------------------------------------------------------------------
__global__ void k_cnt_zero() {
    int n = blockIdx.x * blockDim.x + threadIdx.x;
    if (n < NN) g_cnt[n] = 0;
}

__global__ void k_count(const int* __restrict__ dst) {
    int e = blockIdx.x * blockDim.x + threadIdx.x;
    if (e < NE) atomicAdd(&g_cnt[dst[e]], 1);
}

__global__ void k_dinv() {
    int n = blockIdx.x * blockDim.x + threadIdx.x;
    if (n < NN) g_dinv[n] = rsqrtf(1.0f + (float)g_cnt[n]);
}

// Phase 1: per-block sums of 1024 counts
__global__ __launch_bounds__(1024) void k_blocksum() {
    __shared__ int sm[1024];
    int i = blockIdx.x * 1024 + threadIdx.x;
    int v = (i < NN) ? g_cnt[i] : 0;
    sm[threadIdx.x] = v;
    __syncthreads();
#pragma unroll
    for (int d = 512; d > 0; d >>= 1) {
        if (threadIdx.x < d) sm[threadIdx.x] += sm[threadIdx.x + d];
        __syncthreads();
    }
    if (threadIdx.x == 0) g_bsum[blockIdx.x] = sm[0];
}

// Phase 2: exclusive scan of the NB block sums (one tiny block)
__global__ void k_bscan() {
    __shared__ int sm[128];
    int t = threadIdx.x;
    int v = (t < NB) ? g_bsum[t] : 0;
    sm[t] = v;
    __syncthreads();
#pragma unroll
    for (int d = 1; d < 128; d <<= 1) {
        int x = (t >= d) ? sm[t - d] : 0;
        __syncthreads();
        sm[t] += x;
        __syncthreads();
    }
    if (t < 128) g_bsum[t] = sm[t] - v;  // exclusive
}

// Phase 3: block-local exclusive scan + base -> offsets & cursors
__global__ __launch_bounds__(1024) void k_offsets() {
    __shared__ int sm[1024];
    int i = blockIdx.x * 1024 + threadIdx.x;
    int v = (i < NN) ? g_cnt[i] : 0;
    sm[threadIdx.x] = v;
    __syncthreads();
#pragma unroll
    for (int d = 1; d < 1024; d <<= 1) {
        int x = (threadIdx.x >= d) ? sm[threadIdx.x - d] : 0;
        __syncthreads();
        sm[threadIdx.x] += x;
        __syncthreads();
    }
    if (i < NN) {
        int off = g_bsum[blockIdx.x] + sm[threadIdx.x] - v;  // exclusive
        g_off[i] = off;
        g_cursor[i] = off;
    }
    if (i == 0) g_off[NN] = NE;
}

__global__ void k_scatter(const int* __restrict__ src, const int* __restrict__ dst) {
    int e = blockIdx.x * blockDim.x + threadIdx.x;
    if (e >= NE) return;
    int s = src[e], d = dst[e];
    int pos = atomicAdd(&g_cursor[d], 1);
    g_es[pos] = s;
    g_en[pos] = g_dinv[s] * g_dinv[d];
}

// ---------------------------------------------------------------------------
// FP32 SGEMM, double-buffered: C[M,128] = op(A[M,KT]) @ B[KT,128]
// ---------------------------------------------------------------------------
template <int KT, bool RELU>
__global__ __launch_bounds__(256) void sgemm128(
    const float* __restrict__ A,
    const float* __restrict__ B0, const float* __restrict__ B1, int ldb,
    float* __restrict__ C, int M)
{
    __shared__ float As[2][16][128];
    __shared__ float Bs[2][16][128];

    const int t = threadIdx.x;
    const int tx = t & 15;
    const int ty = t >> 4;
    const int blockRow = blockIdx.x * 128;

    const int ar = t >> 1;
    const int ak = (t & 1) * 8;
    const int grow = blockRow + ar;
    const bool arow_ok = (grow < M);
    const float* aptr = A + (size_t)grow * KT + ak;

    const int bk = t >> 4;
    const int bn = (t & 15) * 8;
    const float* bptr = (bn < 64) ? (B0 + bn) : (B1 + (bn - 64));

    float acc[8][8];
#pragma unroll
    for (int i = 0; i < 8; i++)
#pragma unroll
        for (int j = 0; j < 8; j++) acc[i][j] = 0.0f;

    float4 a0, a1, b0, b1;

    // --- load tile 0 ---
    a0 = make_float4(0.f, 0.f, 0.f, 0.f); a1 = a0;
    if (arow_ok) {
        a0 = *(const float4*)(aptr);
        a1 = *(const float4*)(aptr + 4);
    }
    b0 = *(const float4*)(bptr + (size_t)bk * ldb);
    b1 = *(const float4*)(bptr + (size_t)bk * ldb + 4);

    int cur = 0;
#pragma unroll 1
    for (int kt = 0; kt < KT; kt += 16) {
        // stage current regs into smem buffer `cur`
        if (RELU) {
            a0.x = fmaxf(a0.x, 0.f); a0.y = fmaxf(a0.y, 0.f);
            a0.z = fmaxf(a0.z, 0.f); a0.w = fmaxf(a0.w, 0.f);
            a1.x = fmaxf(a1.x, 0.f); a1.y = fmaxf(a1.y, 0.f);
            a1.z = fmaxf(a1.z, 0.f); a1.w = fmaxf(a1.w, 0.f);
        }
        As[cur][ak + 0][ar] = a0.x; As[cur][ak + 1][ar] = a0.y;
        As[cur][ak + 2][ar] = a0.z; As[cur][ak + 3][ar] = a0.w;
        As[cur][ak + 4][ar] = a1.x; As[cur][ak + 5][ar] = a1.y;
        As[cur][ak + 6][ar] = a1.z; As[cur][ak + 7][ar] = a1.w;
        *(float4*)&Bs[cur][bk][bn] = b0;
        *(float4*)&Bs[cur][bk][bn + 4] = b1;
        __syncthreads();

        // prefetch next tile (overlaps with compute below)
        const int ktn = kt + 16;
        if (ktn < KT) {
            a0 = make_float4(0.f, 0.f, 0.f, 0.f); a1 = a0;
            if (arow_ok) {
                a0 = *(const float4*)(aptr + ktn);
                a1 = *(const float4*)(aptr + ktn + 4);
            }
            b0 = *(const float4*)(bptr + (size_t)(ktn + bk) * ldb);
            b1 = *(const float4*)(bptr + (size_t)(ktn + bk) * ldb + 4);
        }

#pragma unroll
        for (int kk = 0; kk < 16; kk++) {
            float4 fa0 = *(const float4*)&As[cur][kk][ty * 8];
            float4 fa1 = *(const float4*)&As[cur][kk][ty * 8 + 4];
            float4 fb0 = *(const float4*)&Bs[cur][kk][tx * 8];
            float4 fb1 = *(const float4*)&Bs[cur][kk][tx * 8 + 4];
            float a[8] = {fa0.x, fa0.y, fa0.z, fa0.w, fa1.x, fa1.y, fa1.z, fa1.w};
            float b[8] = {fb0.x, fb0.y, fb0.z, fb0.w, fb1.x, fb1.y, fb1.z, fb1.w};
#pragma unroll
            for (int i = 0; i < 8; i++)
#pragma unroll
                for (int j = 0; j < 8; j++)
                    acc[i][j] = fmaf(a[i], b[j], acc[i][j]);
        }
        cur ^= 1;
    }

#pragma unroll
    for (int i = 0; i < 8; i++) {
        int row = blockRow + ty * 8 + i;
        if (row < M) {
            float4 c0 = make_float4(acc[i][0], acc[i][1], acc[i][2], acc[i][3]);
            float4 c1 = make_float4(acc[i][4], acc[i][5], acc[i][6], acc[i][7]);
            *(float4*)(C + (size_t)row * 128 + tx * 8) = c0;
            *(float4*)(C + (size_t)row * 128 + tx * 8 + 4) = c1;
        }
    }
}

// ---------------------------------------------------------------------------
// CSR propagation: warp per node, lane owns 4 channels. No atomics.
// ---------------------------------------------------------------------------
__global__ __launch_bounds__(256) void k_prop_csr(
    const float* __restrict__ H,
    const float* __restrict__ b,
    float* __restrict__ out)
{
    int warp = (blockIdx.x * blockDim.x + threadIdx.x) >> 5;
    if (warp >= NN) return;
    int lane = threadIdx.x & 31;

    float di = g_dinv[warp];
    float s = di * di;
    float4 bb = ((const float4*)b)[lane];
    float4 v = ((const float4*)(H + (size_t)warp * HID))[lane];
    float ax = fmaf(v.x, s, bb.x);
    float ay = fmaf(v.y, s, bb.y);
    float az = fmaf(v.z, s, bb.z);
    float aw = fmaf(v.w, s, bb.w);

    int e = g_off[warp];
    const int end = g_off[warp + 1];
    for (; e + 1 < end; e += 2) {
        int s0 = g_es[e],     s1 = g_es[e + 1];
        float n0 = g_en[e],   n1 = g_en[e + 1];
        float4 v0 = ((const float4*)(H + (size_t)s0 * HID))[lane];
        float4 v1 = ((const float4*)(H + (size_t)s1 * HID))[lane];
        ax = fmaf(v0.x, n0, ax); ay = fmaf(v0.y, n0, ay);
        az = fmaf(v0.z, n0, az); aw = fmaf(v0.w, n0, aw);
        ax = fmaf(v1.x, n1, ax); ay = fmaf(v1.y, n1, ay);
        az = fmaf(v1.z, n1, az); aw = fmaf(v1.w, n1, aw);
    }
    if (e < end) {
        int s0 = g_es[e];
        float n0 = g_en[e];
        float4 v0 = ((const float4*)(H + (size_t)s0 * HID))[lane];
        ax = fmaf(v0.x, n0, ax); ay = fmaf(v0.y, n0, ay);
        az = fmaf(v0.z, n0, az); aw = fmaf(v0.w, n0, aw);
    }

    ((float4*)(out + (size_t)warp * HID))[lane] = make_float4(ax, ay, az, aw);
}

// Layer-2 variant: lanes 0..15 -> mu, 16..31 -> logvar (split output)
__global__ __launch_bounds__(256) void k_prop_csr_out(
    const float* __restrict__ H,
    const float* __restrict__ bmu,
    const float* __restrict__ blv,
    float* __restrict__ out)
{
    int warp = (blockIdx.x * blockDim.x + threadIdx.x) >> 5;
    if (warp >= NN) return;
    int lane = threadIdx.x & 31;

    float di = g_dinv[warp];
    float s = di * di;
    float4 bb;
    float* dstp;
    if (lane < 16) {
        bb = ((const float4*)bmu)[lane];
        dstp = out + (size_t)warp * 64 + lane * 4;
    } else {
        bb = ((const float4*)blv)[lane - 16];
        dstp = out + (size_t)NN * 64 + (size_t)warp * 64 + (lane - 16) * 4;
    }
    float4 v = ((const float4*)(H + (size_t)warp * HID))[lane];
    float ax = fmaf(v.x, s, bb.x);
    float ay = fmaf(v.y, s, bb.y);
    float az = fmaf(v.z, s, bb.z);
    float aw = fmaf(v.w, s, bb.w);

    int e = g_off[warp];
    const int end = g_off[warp + 1];
    for (; e + 1 < end; e += 2) {
        int s0 = g_es[e],     s1 = g_es[e + 1];
        float n0 = g_en[e],   n1 = g_en[e + 1];
        float4 v0 = ((const float4*)(H + (size_t)s0 * HID))[lane];
        float4 v1 = ((const float4*)(H + (size_t)s1 * HID))[lane];
        ax = fmaf(v0.x, n0, ax); ay = fmaf(v0.y, n0, ay);
        az = fmaf(v0.z, n0, az); aw = fmaf(v0.w, n0, aw);
        ax = fmaf(v1.x, n1, ax); ay = fmaf(v1.y, n1, ay);
        az = fmaf(v1.z, n1, az); aw = fmaf(v1.w, n1, aw);
    }
    if (e < end) {
        int s0 = g_es[e];
        float n0 = g_en[e];
        float4 v0 = ((const float4*)(H + (size_t)s0 * HID))[lane];
        ax = fmaf(v0.x, n0, ax); ay = fmaf(v0.y, n0, ay);
        az = fmaf(v0.z, n0, az); aw = fmaf(v0.w, n0, aw);
    }

    *(float4*)dstp = make_float4(ax, ay, az, aw);
}

// ---------------------------------------------------------------------------
extern "C" void kernel_launch(void* const* d_in, const int* in_sizes, int n_in,
                              void* d_out, int out_size)
{
    const float* x   = (const float*)d_in[0];
    const int*   ei  = (const int*)d_in[1];
    const float* W1  = (const float*)d_in[2];
    const float* b1  = (const float*)d_in[3];
    const float* Wmu = (const float*)d_in[4];
    const float* bmu = (const float*)d_in[5];
    const float* Wlv = (const float*)d_in[6];
    const float* blv = (const float*)d_in[7];
    float* out = (float*)d_out;

    const int* src = ei;
    const int* dst = ei + NE;

    float *h_ptr, *p_ptr;
    cudaGetSymbolAddress((void**)&h_ptr, g_h);
    cudaGetSymbolAddress((void**)&p_ptr, g_p);

    const int TB = 256;

    // --- CSR build ---
    k_cnt_zero<<<(NN + TB - 1) / TB, TB>>>();
    k_count<<<(NE + TB - 1) / TB, TB>>>(dst);
    k_dinv<<<(NN + TB - 1) / TB, TB>>>();
    k_blocksum<<<NB, 1024>>>();
    k_bscan<<<1, 128>>>();
    k_offsets<<<NB, 1024>>>();
    k_scatter<<<(NE + TB - 1) / TB, TB>>>(src, dst);

    // --- Layer 1: h1 = x @ W1 ---
    sgemm128<INC, false><<<(NN + 127) / 128, 256>>>(x, W1, W1 + 64, 128, h_ptr, NN);

    // --- Propagate hidden (CSR, no atomics) ---
    k_prop_csr<<<(NN * 32 + TB - 1) / TB, TB>>>(h_ptr, b1, p_ptr);

    // --- Layer 2 pre: h2 = relu(p) @ [W_mu | W_logvar] ---
    sgemm128<HID, true><<<(NN + 127) / 128, 256>>>(p_ptr, Wmu, Wlv, 64, h_ptr, NN);

    // --- Propagate to split output ---
    k_prop_csr_out<<<(NN * 32 + TB - 1) / TB, TB>>>(h_ptr, bmu, blv, out);
}